// round 1
// baseline (speedup 1.0000x reference)
#include <cuda_runtime.h>
#include <math.h>

// ---------------------------------------------------------------------------
// MoE: T=2048 tokens, D=1024, E=16 experts top-2, INTER=512, shared INTER=1024
// Strategy: exploit top-2 sparsity (ref computes densely).
//   1. gate  -> top2 per token, per-expert counts
//   2. offsets + scatter -> compact per-expert slot lists (4096 slots total)
//   3. routed SwiGLU GEMM (gathered rows) -> g_h
//   4. routed down GEMM -> g_rout
//   5. shared SwiGLU GEMM -> g_hs ; shared down GEMM -> d_out
//   6. combine: out += w0*rout[slot0] + w1*rout[slot1]
// All fp32 SIMT (64x64x16 tiles). Tensor cores come next round.
// ---------------------------------------------------------------------------

namespace {
constexpr int T     = 2048;
constexpr int DIMC  = 1024;
constexpr int E     = 16;
constexpr int NP    = T * 2;      // 4096 (token,expert) pairs
constexpr int INTER = 512;
constexpr int SI    = 1024;       // shared inter

constexpr int BM = 64, BN = 64, BK = 16;
}

// scratch (static device globals: allocation-free rule)
__device__ int   g_count[E];
__device__ int   g_offset[E];
__device__ int   g_fill[E];
__device__ int   g_pair_e[NP];
__device__ float g_pair_w[NP];
__device__ int   g_slot_of_pair[NP];
__device__ int   g_tok_of_slot[NP];
__device__ float g_h[(size_t)NP * INTER];     //  8 MB
__device__ float g_rout[(size_t)NP * DIMC];   // 16 MB
__device__ float g_hs[(size_t)T * SI];        //  8 MB

// ---------------------------------------------------------------------------
__global__ void reset_kernel() {
    int i = threadIdx.x;
    if (i < E) g_count[i] = 0;
}

// one block per token: scores = sigmoid(x @ gate_w^T), top-2, normalized weights
__global__ __launch_bounds__(128) void gate_kernel(const float* __restrict__ x,
                                                   const float* __restrict__ gw) {
    __shared__ float xs[DIMC];
    __shared__ float part[8][E];
    __shared__ float logit[E];
    int t = blockIdx.x;
    for (int i = threadIdx.x; i < DIMC; i += 128) xs[i] = x[(size_t)t * DIMC + i];
    __syncthreads();

    int e = threadIdx.x & 15;
    int chunk = threadIdx.x >> 4;          // 0..7, 128 elems each
    const float* gr = gw + (size_t)e * DIMC + chunk * 128;
    const float* xr = xs + chunk * 128;
    float a0 = 0.f, a1 = 0.f, a2 = 0.f, a3 = 0.f;
    #pragma unroll 8
    for (int i = 0; i < 128; i += 4) {
        a0 += xr[i+0] * gr[i+0];
        a1 += xr[i+1] * gr[i+1];
        a2 += xr[i+2] * gr[i+2];
        a3 += xr[i+3] * gr[i+3];
    }
    part[chunk][e] = (a0 + a1) + (a2 + a3);
    __syncthreads();
    if (threadIdx.x < E) {
        float s = 0.f;
        #pragma unroll
        for (int c = 0; c < 8; c++) s += part[c][threadIdx.x];
        logit[threadIdx.x] = s;
    }
    __syncthreads();
    if (threadIdx.x == 0) {
        int i0 = 0; float v0 = logit[0];
        #pragma unroll
        for (int i = 1; i < E; i++) if (logit[i] > v0) { v0 = logit[i]; i0 = i; }
        int i1 = -1; float v1 = -1e30f;
        #pragma unroll
        for (int i = 0; i < E; i++) if (i != i0 && logit[i] > v1) { v1 = logit[i]; i1 = i; }
        float s0 = 1.f / (1.f + expf(-v0));
        float s1 = 1.f / (1.f + expf(-v1));
        float inv = 1.f / (s0 + s1);
        g_pair_e[t*2+0] = i0;  g_pair_w[t*2+0] = s0 * inv;
        g_pair_e[t*2+1] = i1;  g_pair_w[t*2+1] = s1 * inv;
        atomicAdd(&g_count[i0], 1);
        atomicAdd(&g_count[i1], 1);
    }
}

__global__ void offsets_kernel() {
    if (threadIdx.x == 0) {
        int s = 0;
        for (int e = 0; e < E; e++) { g_offset[e] = s; s += g_count[e]; g_fill[e] = 0; }
    }
}

__global__ void scatter_kernel() {
    int p = blockIdx.x * blockDim.x + threadIdx.x;
    if (p >= NP) return;
    int e = g_pair_e[p];
    int pos = atomicAdd(&g_fill[e], 1);
    int slot = g_offset[e] + pos;
    g_slot_of_pair[p] = slot;
    g_tok_of_slot[slot] = p >> 1;
}

// ---------------------------------------------------------------------------
// Generic 64x64x16 fp32 tile GEMM: C = A @ B^T (both K-major), optional dual-B
// SwiGLU epilogue, optional per-expert routing with row gather.
//   ASRC: 0=Aext, 1=g_h, 2=g_hs     CDST: 0=g_h, 1=g_rout, 2=g_hs, 3=Cext
// ---------------------------------------------------------------------------
template<int KD, bool DUAL, bool ROUTED, bool GATHER, int ASRC, int CDST>
__global__ __launch_bounds__(256) void gemm_tile(const float* __restrict__ Aext,
                                                 const float* __restrict__ B1g,
                                                 const float* __restrict__ B3g,
                                                 float* __restrict__ Cext,
                                                 int Mtot, int Ntot) {
    const float* A = (ASRC == 0) ? Aext : (ASRC == 1 ? g_h : g_hs);
    float* C = (CDST == 0) ? g_h : (CDST == 1 ? g_rout : (CDST == 2 ? g_hs : Cext));

    const int e    = ROUTED ? blockIdx.z : 0;
    const int cnt  = ROUTED ? g_count[e] : Mtot;
    const int m0   = blockIdx.x * BM;
    if (m0 >= cnt) return;
    const int n0   = blockIdx.y * BN;
    const int base = ROUTED ? g_offset[e] : 0;

    const float* B1 = B1g + (size_t)(ROUTED ? e : 0) * Ntot * KD;
    const float* B3 = DUAL ? (B3g + (size_t)(ROUTED ? e : 0) * Ntot * KD) : nullptr;

    __shared__ float As [BK][BM + 4];
    __shared__ float Bs1[BK][BN + 4];
    __shared__ float Bs3[DUAL ? BK : 1][BN + 4];
    __shared__ int   rows[BM];

    const int tid = threadIdx.x;
    if (tid < BM) {
        int m = m0 + tid;
        int r = -1;
        if (m < cnt) {
            if (GATHER)      r = g_tok_of_slot[base + m];
            else if (ROUTED) r = base + m;
            else             r = m;
        }
        rows[tid] = r;
    }
    __syncthreads();

    float acc1[4][4] = {};
    float acc3[4][4] = {};
    const int tx = tid & 15;          // n micro
    const int ty = tid >> 4;          // m micro
    const int lr = tid >> 2;          // load row 0..63
    const int lc = (tid & 3) << 2;    // load col 0,4,8,12

    const int ar = rows[lr];
    const float* aptr  = (ar >= 0) ? (A + (size_t)ar * KD + lc) : nullptr;
    const float* b1ptr = B1 + (size_t)(n0 + lr) * KD + lc;
    const float* b3ptr = DUAL ? (B3 + (size_t)(n0 + lr) * KD + lc) : nullptr;

    for (int k0 = 0; k0 < KD; k0 += BK) {
        float4 av = aptr ? *(const float4*)(aptr + k0) : make_float4(0.f, 0.f, 0.f, 0.f);
        As[lc+0][lr] = av.x; As[lc+1][lr] = av.y; As[lc+2][lr] = av.z; As[lc+3][lr] = av.w;
        float4 bv = *(const float4*)(b1ptr + k0);
        Bs1[lc+0][lr] = bv.x; Bs1[lc+1][lr] = bv.y; Bs1[lc+2][lr] = bv.z; Bs1[lc+3][lr] = bv.w;
        if (DUAL) {
            float4 cv = *(const float4*)(b3ptr + k0);
            Bs3[lc+0][lr] = cv.x; Bs3[lc+1][lr] = cv.y; Bs3[lc+2][lr] = cv.z; Bs3[lc+3][lr] = cv.w;
        }
        __syncthreads();

        #pragma unroll
        for (int kk = 0; kk < BK; kk++) {
            float4 ra  = *(const float4*)(&As[kk][ty * 4]);
            float4 rb  = *(const float4*)(&Bs1[kk][tx * 4]);
            float a[4] = {ra.x, ra.y, ra.z, ra.w};
            float b[4] = {rb.x, rb.y, rb.z, rb.w};
            if (DUAL) {
                float4 rc  = *(const float4*)(&Bs3[kk][tx * 4]);
                float c[4] = {rc.x, rc.y, rc.z, rc.w};
                #pragma unroll
                for (int i = 0; i < 4; i++)
                    #pragma unroll
                    for (int j = 0; j < 4; j++) {
                        acc1[i][j] += a[i] * b[j];
                        acc3[i][j] += a[i] * c[j];
                    }
            } else {
                #pragma unroll
                for (int i = 0; i < 4; i++)
                    #pragma unroll
                    for (int j = 0; j < 4; j++)
                        acc1[i][j] += a[i] * b[j];
            }
        }
        __syncthreads();
    }

    #pragma unroll
    for (int i = 0; i < 4; i++) {
        int m = m0 + ty * 4 + i;
        if (m >= cnt) continue;
        size_t orow = (size_t)(ROUTED ? (base + m) : m) * Ntot + n0 + tx * 4;
        float4 o;
        if (DUAL) {
            float c10 = acc1[i][0], c11 = acc1[i][1], c12 = acc1[i][2], c13 = acc1[i][3];
            o.x = (c10 / (1.f + expf(-c10))) * acc3[i][0];
            o.y = (c11 / (1.f + expf(-c11))) * acc3[i][1];
            o.z = (c12 / (1.f + expf(-c12))) * acc3[i][2];
            o.w = (c13 / (1.f + expf(-c13))) * acc3[i][3];
        } else {
            o.x = acc1[i][0]; o.y = acc1[i][1]; o.z = acc1[i][2]; o.w = acc1[i][3];
        }
        *(float4*)(C + orow) = o;
    }
}

// out[t] (already = shared expert z) += w0*rout[slot0] + w1*rout[slot1]
__global__ __launch_bounds__(256) void combine_kernel(float* __restrict__ out) {
    int t = blockIdx.x;
    float w0 = g_pair_w[t*2+0], w1 = g_pair_w[t*2+1];
    size_t s0 = (size_t)g_slot_of_pair[t*2+0] * DIMC;
    size_t s1 = (size_t)g_slot_of_pair[t*2+1] * DIMC;
    int d = threadIdx.x * 4;
    float4 o  = *(float4*)(out + (size_t)t * DIMC + d);
    float4 r0 = *(const float4*)(g_rout + s0 + d);
    float4 r1 = *(const float4*)(g_rout + s1 + d);
    o.x += w0 * r0.x + w1 * r1.x;
    o.y += w0 * r0.y + w1 * r1.y;
    o.z += w0 * r0.z + w1 * r1.z;
    o.w += w0 * r0.w + w1 * r1.w;
    *(float4*)(out + (size_t)t * DIMC + d) = o;
}

// ---------------------------------------------------------------------------
extern "C" void kernel_launch(void* const* d_in, const int* in_sizes, int n_in,
                              void* d_out, int out_size) {
    const float* x      = (const float*)d_in[0];
    const float* gate_w = (const float*)d_in[1];
    const float* w1     = (const float*)d_in[2];
    const float* w2     = (const float*)d_in[3];
    const float* w3     = (const float*)d_in[4];
    const float* sw1    = (const float*)d_in[5];
    const float* sw2    = (const float*)d_in[6];
    const float* sw3    = (const float*)d_in[7];
    float* out = (float*)d_out;

    reset_kernel<<<1, 32>>>();
    gate_kernel<<<T, 128>>>(x, gate_w);
    offsets_kernel<<<1, 32>>>();
    scatter_kernel<<<NP / 256, 256>>>();

    // routed SwiGLU: h[slot, 512] = silu(x@w1_e^T) * (x@w3_e^T)
    gemm_tile<DIMC, true, true, true, 0, 0>
        <<<dim3(T / BM, INTER / BN, E), 256>>>(x, w1, w3, nullptr, T, INTER);
    // routed down: rout[slot, 1024] = h @ w2_e^T
    gemm_tile<INTER, false, true, false, 1, 1>
        <<<dim3(T / BM, DIMC / BN, E), 256>>>(nullptr, w2, nullptr, nullptr, T, DIMC);
    // shared SwiGLU: hs[t, 1024] = silu(x@sw1^T) * (x@sw3^T)
    gemm_tile<DIMC, true, false, false, 0, 2>
        <<<dim3(T / BM, SI / BN, 1), 256>>>(x, sw1, sw3, nullptr, T, SI);
    // shared down -> d_out directly
    gemm_tile<SI, false, false, false, 2, 3>
        <<<dim3(T / BM, DIMC / BN, 1), 256>>>(nullptr, sw2, nullptr, out, T, DIMC);

    combine_kernel<<<T, 256>>>(out);
}

// round 3
// speedup vs baseline: 3.4048x; 3.4048x over previous
#include <cuda_runtime.h>
#include <cstdint>
#include <math.h>

// ---------------------------------------------------------------------------
// MoE via legacy tensor-core mma.sync (tf32), since this harness's PTX target
// is plain sm_103 (tcgen05 rejected by ptxas).
//   gate -> offsets -> scatter (fp32, exact routing)
//   GEMM1 routed SwiGLU (gather, dual-B) -> g_h
//   GEMM2 routed down                    -> g_rout
//   GEMM3 shared SwiGLU (dual-B)         -> g_hs
//   GEMM4 shared down                    -> d_out
//   combine: out += w0*rout[s0] + w1*rout[s1]
// GEMM: block 64x128, 8 warps (2x4), warp 32x32, mma.m16n8k8 tf32.
// ---------------------------------------------------------------------------

namespace {
constexpr int T     = 2048;
constexpr int DIMC  = 1024;
constexpr int E     = 16;
constexpr int NP    = T * 2;
constexpr int INTER = 512;
constexpr int SI    = 1024;

constexpr int BM = 64, BN = 128, BK = 16;   // two k-steps of 8 per stage
constexpr int PAD = 12;                     // floats per 8-k group row (bank-safe)
}

__device__ int   g_count[E];
__device__ int   g_offset[E];
__device__ int   g_fill[E];
__device__ int   g_pair_e[NP];
__device__ float g_pair_w[NP];
__device__ int   g_slot_of_pair[NP];
__device__ int   g_tok_of_slot[NP];
__device__ float g_h[(size_t)NP * INTER];
__device__ float g_rout[(size_t)NP * DIMC];
__device__ float g_hs[(size_t)T * SI];

// ---------------- helpers ----------------
__device__ __forceinline__ uint32_t f2tf32(float f) {
    uint32_t r;
    asm("cvt.rna.tf32.f32 %0, %1;" : "=r"(r) : "f"(f));
    return r;
}
__device__ __forceinline__ void mma8(float* c, const uint32_t* a, const uint32_t* b) {
    asm volatile(
        "mma.sync.aligned.m16n8k8.row.col.f32.tf32.tf32.f32 "
        "{%0,%1,%2,%3},{%4,%5,%6,%7},{%8,%9},{%0,%1,%2,%3};"
        : "+f"(c[0]), "+f"(c[1]), "+f"(c[2]), "+f"(c[3])
        : "r"(a[0]), "r"(a[1]), "r"(a[2]), "r"(a[3]), "r"(b[0]), "r"(b[1]));
}

// ---------------- routing ----------------
__global__ void reset_kernel() {
    if (threadIdx.x < E) g_count[threadIdx.x] = 0;
}

__global__ __launch_bounds__(128) void gate_kernel(const float* __restrict__ x,
                                                   const float* __restrict__ gw) {
    __shared__ float xs[DIMC];
    __shared__ float part[8][E];
    __shared__ float logit[E];
    int t = blockIdx.x;
    for (int i = threadIdx.x; i < DIMC; i += 128) xs[i] = x[(size_t)t * DIMC + i];
    __syncthreads();
    int e = threadIdx.x & 15, chunk = threadIdx.x >> 4;
    const float* gr = gw + (size_t)e * DIMC + chunk * 128;
    const float* xr = xs + chunk * 128;
    float a0 = 0.f, a1 = 0.f, a2 = 0.f, a3 = 0.f;
    #pragma unroll 8
    for (int i = 0; i < 128; i += 4) {
        a0 += xr[i+0] * gr[i+0]; a1 += xr[i+1] * gr[i+1];
        a2 += xr[i+2] * gr[i+2]; a3 += xr[i+3] * gr[i+3];
    }
    part[chunk][e] = (a0 + a1) + (a2 + a3);
    __syncthreads();
    if (threadIdx.x < E) {
        float s = 0.f;
        #pragma unroll
        for (int c = 0; c < 8; c++) s += part[c][threadIdx.x];
        logit[threadIdx.x] = s;
    }
    __syncthreads();
    if (threadIdx.x == 0) {
        int i0 = 0; float v0 = logit[0];
        #pragma unroll
        for (int i = 1; i < E; i++) if (logit[i] > v0) { v0 = logit[i]; i0 = i; }
        int i1 = -1; float v1 = -1e30f;
        #pragma unroll
        for (int i = 0; i < E; i++) if (i != i0 && logit[i] > v1) { v1 = logit[i]; i1 = i; }
        float s0 = 1.f / (1.f + expf(-v0));
        float s1 = 1.f / (1.f + expf(-v1));
        float inv = 1.f / (s0 + s1);
        g_pair_e[t*2+0] = i0; g_pair_w[t*2+0] = s0 * inv;
        g_pair_e[t*2+1] = i1; g_pair_w[t*2+1] = s1 * inv;
        atomicAdd(&g_count[i0], 1);
        atomicAdd(&g_count[i1], 1);
    }
}

__global__ void offsets_kernel() {
    if (threadIdx.x == 0) {
        int s = 0;
        for (int e = 0; e < E; e++) { g_offset[e] = s; s += g_count[e]; g_fill[e] = 0; }
    }
}

__global__ void scatter_kernel() {
    int p = blockIdx.x * blockDim.x + threadIdx.x;
    if (p >= NP) return;
    int e = g_pair_e[p];
    int slot = g_offset[e] + atomicAdd(&g_fill[e], 1);
    g_slot_of_pair[p] = slot;
    g_tok_of_slot[slot] = p >> 1;
}

// ---------------------------------------------------------------------------
// tf32 mma.sync tile GEMM: C[M,N] = A[M,K] @ B[N,K]^T  (+ dual-B SwiGLU)
//   ASRC: 0=ext, 1=g_h, 2=g_hs    CDST: 0=g_h, 1=g_rout, 2=g_hs, 3=ext
// ---------------------------------------------------------------------------
template<int KD, bool DUAL, bool ROUTED, bool GATHER, int ASRC, int CDST>
__global__ __launch_bounds__(256) void gemm_mma(const float* __restrict__ Aext,
                                                const float* __restrict__ B1g,
                                                const float* __restrict__ B3g,
                                                float* __restrict__ Cext,
                                                int Ntot) {
    const int e   = ROUTED ? blockIdx.z : 0;
    const int cnt = ROUTED ? g_count[e] : T;
    const int m0  = blockIdx.x * BM;
    if (m0 >= cnt) return;
    const int n0   = blockIdx.y * BN;
    const int base = ROUTED ? g_offset[e] : 0;

    const float* A = (ASRC == 0) ? Aext : (ASRC == 1 ? g_h : g_hs);
    float* C = (CDST == 0) ? g_h : (CDST == 1 ? g_rout : (CDST == 2 ? g_hs : Cext));
    const float* B1 = B1g + (size_t)(ROUTED ? e : 0) * Ntot * KD;
    const float* B3 = DUAL ? (B3g + (size_t)(ROUTED ? e : 0) * Ntot * KD) : nullptr;

    __shared__ uint32_t As [2 * BM * PAD];            // [kgroup][m][PAD]
    __shared__ uint32_t B1s[2 * BN * PAD];            // [kgroup][n][PAD]
    __shared__ uint32_t B3s[DUAL ? 2 * BN * PAD : 1];
    __shared__ int rowsS[BM];

    const int tid    = threadIdx.x;
    const int wid    = tid >> 5;
    const int lane   = tid & 31;
    const int lane4  = lane >> 2;       // 0..7
    const int lanek  = lane & 3;        // 0..3
    const int warp_m = wid & 1;         // 2
    const int warp_n = wid >> 1;        // 4

    if (tid < BM) {
        int m = m0 + tid;
        int r;
        if (m >= cnt)    r = GATHER ? g_tok_of_slot[base] : base;   // clamp, masked later
        else if (GATHER) r = g_tok_of_slot[base + m];
        else if (ROUTED) r = base + m;
        else             r = m;
        rowsS[tid] = r;
    }
    __syncthreads();

    // gmem load addressing: each thread handles float4s
    const int lr = tid >> 2;            // 0..63
    const int lq = tid & 3;             // 0..3
    const int lg = lq >> 1;             // kgroup 0/1
    const int lk = (lq & 1) * 4;        // kin 0/4
    const int a_row = rowsS[lr];
    const float* aload  = A + (size_t)a_row * KD + lg * 8 + lk;
    const float* b1l0   = B1 + (size_t)(n0 + lr)      * KD + lg * 8 + lk;
    const float* b1l1   = B1 + (size_t)(n0 + lr + 64) * KD + lg * 8 + lk;
    const float* b3l0   = DUAL ? (B3 + (size_t)(n0 + lr)      * KD + lg * 8 + lk) : nullptr;
    const float* b3l1   = DUAL ? (B3 + (size_t)(n0 + lr + 64) * KD + lg * 8 + lk) : nullptr;
    uint32_t* asw  = As  + (lg * BM + lr) * PAD + lk;
    uint32_t* b1w0 = B1s + (lg * BN + lr) * PAD + lk;
    uint32_t* b1w1 = B1s + (lg * BN + lr + 64) * PAD + lk;
    uint32_t* b3w0 = DUAL ? (B3s + (lg * BN + lr) * PAD + lk) : nullptr;
    uint32_t* b3w1 = DUAL ? (B3s + (lg * BN + lr + 64) * PAD + lk) : nullptr;

    float acc1[2][4][4] = {};
    float acc3[2][4][4] = {};

    for (int k0 = 0; k0 < KD; k0 += BK) {
        {
            float4 v = *(const float4*)(aload + k0);
            asw[0] = f2tf32(v.x); asw[1] = f2tf32(v.y);
            asw[2] = f2tf32(v.z); asw[3] = f2tf32(v.w);
            v = *(const float4*)(b1l0 + k0);
            b1w0[0] = f2tf32(v.x); b1w0[1] = f2tf32(v.y);
            b1w0[2] = f2tf32(v.z); b1w0[3] = f2tf32(v.w);
            v = *(const float4*)(b1l1 + k0);
            b1w1[0] = f2tf32(v.x); b1w1[1] = f2tf32(v.y);
            b1w1[2] = f2tf32(v.z); b1w1[3] = f2tf32(v.w);
            if (DUAL) {
                v = *(const float4*)(b3l0 + k0);
                b3w0[0] = f2tf32(v.x); b3w0[1] = f2tf32(v.y);
                b3w0[2] = f2tf32(v.z); b3w0[3] = f2tf32(v.w);
                v = *(const float4*)(b3l1 + k0);
                b3w1[0] = f2tf32(v.x); b3w1[1] = f2tf32(v.y);
                b3w1[2] = f2tf32(v.z); b3w1[3] = f2tf32(v.w);
            }
        }
        __syncthreads();

        #pragma unroll
        for (int ks = 0; ks < 2; ks++) {
            const uint32_t* Ab  = As  + ks * BM * PAD;
            const uint32_t* B1b = B1s + ks * BN * PAD;
            const uint32_t* B3b = DUAL ? (B3s + ks * BN * PAD) : nullptr;
            uint32_t af[2][4];
            #pragma unroll
            for (int fm = 0; fm < 2; fm++) {
                int rbase = (warp_m * 32 + fm * 16 + lane4) * PAD + lanek;
                af[fm][0] = Ab[rbase];
                af[fm][1] = Ab[rbase + 8 * PAD];
                af[fm][2] = Ab[rbase + 4];
                af[fm][3] = Ab[rbase + 8 * PAD + 4];
            }
            #pragma unroll
            for (int fn = 0; fn < 4; fn++) {
                int nbase = (warp_n * 32 + fn * 8 + lane4) * PAD + lanek;
                uint32_t bf[2];
                bf[0] = B1b[nbase];
                bf[1] = B1b[nbase + 4];
                #pragma unroll
                for (int fm = 0; fm < 2; fm++) mma8(acc1[fm][fn], af[fm], bf);
                if (DUAL) {
                    uint32_t cf[2];
                    cf[0] = B3b[nbase];
                    cf[1] = B3b[nbase + 4];
                    #pragma unroll
                    for (int fm = 0; fm < 2; fm++) mma8(acc3[fm][fn], af[fm], cf);
                }
            }
        }
        __syncthreads();
    }

    // epilogue
    #pragma unroll
    for (int fm = 0; fm < 2; fm++) {
        #pragma unroll
        for (int half = 0; half < 2; half++) {
            int mi = warp_m * 32 + fm * 16 + half * 8 + lane4;
            int m  = m0 + mi;
            if (m >= cnt) continue;
            size_t crow = ROUTED ? (size_t)(base + m) : (size_t)m;
            float* cp = C + crow * Ntot + n0 + warp_n * 32 + lanek * 2;
            #pragma unroll
            for (int fn = 0; fn < 4; fn++) {
                float v0 = acc1[fm][fn][half * 2 + 0];
                float v1 = acc1[fm][fn][half * 2 + 1];
                float2 o;
                if (DUAL) {
                    o.x = (v0 / (1.f + __expf(-v0))) * acc3[fm][fn][half * 2 + 0];
                    o.y = (v1 / (1.f + __expf(-v1))) * acc3[fm][fn][half * 2 + 1];
                } else {
                    o.x = v0; o.y = v1;
                }
                *(float2*)(cp + fn * 8) = o;
            }
        }
    }
}

__global__ __launch_bounds__(256) void combine_kernel(float* __restrict__ out) {
    int t = blockIdx.x;
    float w0 = g_pair_w[t*2+0], w1 = g_pair_w[t*2+1];
    size_t s0 = (size_t)g_slot_of_pair[t*2+0] * DIMC;
    size_t s1 = (size_t)g_slot_of_pair[t*2+1] * DIMC;
    int d = threadIdx.x * 4;
    float4 o  = *(float4*)(out + (size_t)t * DIMC + d);
    float4 r0 = *(const float4*)(g_rout + s0 + d);
    float4 r1 = *(const float4*)(g_rout + s1 + d);
    o.x += w0 * r0.x + w1 * r1.x;
    o.y += w0 * r0.y + w1 * r1.y;
    o.z += w0 * r0.z + w1 * r1.z;
    o.w += w0 * r0.w + w1 * r1.w;
    *(float4*)(out + (size_t)t * DIMC + d) = o;
}

// ---------------------------------------------------------------------------
extern "C" void kernel_launch(void* const* d_in, const int* in_sizes, int n_in,
                              void* d_out, int out_size) {
    const float* x      = (const float*)d_in[0];
    const float* gate_w = (const float*)d_in[1];
    const float* w1     = (const float*)d_in[2];
    const float* w2     = (const float*)d_in[3];
    const float* w3     = (const float*)d_in[4];
    const float* sw1    = (const float*)d_in[5];
    const float* sw2    = (const float*)d_in[6];
    const float* sw3    = (const float*)d_in[7];
    float* out = (float*)d_out;

    reset_kernel<<<1, 32>>>();
    gate_kernel<<<T, 128>>>(x, gate_w);
    offsets_kernel<<<1, 32>>>();
    scatter_kernel<<<NP / 256, 256>>>();

    // routed SwiGLU: h[slot, 512]
    gemm_mma<DIMC, true, true, true, 0, 0>
        <<<dim3(T / BM, INTER / BN, E), 256>>>(x, w1, w3, nullptr, INTER);
    // routed down: rout[slot, 1024]
    gemm_mma<INTER, false, true, false, 1, 1>
        <<<dim3(T / BM, DIMC / BN, E), 256>>>(nullptr, w2, nullptr, nullptr, DIMC);
    // shared SwiGLU: hs[t, 1024]
    gemm_mma<DIMC, true, false, false, 0, 2>
        <<<dim3(T / BM, SI / BN, 1), 256>>>(x, sw1, sw3, nullptr, SI);
    // shared down -> out
    gemm_mma<SI, false, false, false, 2, 3>
        <<<dim3(T / BM, DIMC / BN, 1), 256>>>(nullptr, sw2, nullptr, out, DIMC);

    combine_kernel<<<T, 256>>>(out);
}